// round 12
// baseline (speedup 1.0000x reference)
#include <cuda_runtime.h>
#include <cuda_bf16.h>
#include <cstdint>

#define N_NODES 1000
#define HIDDEN  256
#define IN_DIM  128
#define N_EDGES 64000

// Scratch (device globals: no allocation allowed)
__device__ float g_C[N_NODES * HIDDEN];   // A - B + b1   (per node)
__device__ float g_B[N_NODES * HIDDEN];   // B = X @ W1b^T (per node)
__device__ float g_H[N_NODES * HIDDEN];   // node features between layers
__device__ float g_mC[N_NODES];           // per-node max of C row
__device__ float g_mB[N_NODES];           // per-node max of B row
__device__ char  g_Wqh[HIDDEN * HIDDEN];  // W2 hi int8 ([n][k] k-major)
__device__ char  g_Wql[HIDDEN * HIDDEN];  // W2 lo int8 (step sw/128)
__device__ float g_sw[HIDDEN];            // per-n W scale
__device__ int   g_src[N_EDGES];
__device__ int   g_dst[N_EDGES];

// ---------------------------------------------------------------------------
__device__ __forceinline__ void mma_s8(int* d, const uint32_t* a,
                                       const uint32_t* b) {
    asm volatile(
        "mma.sync.aligned.m16n8k32.row.col.s32.s8.s8.s32 "
        "{%0,%1,%2,%3}, {%4,%5,%6,%7}, {%8,%9}, {%0,%1,%2,%3};"
        : "+r"(d[0]), "+r"(d[1]), "+r"(d[2]), "+r"(d[3])
        : "r"(a[0]), "r"(a[1]), "r"(a[2]), "r"(a[3]), "r"(b[0]), "r"(b[1]));
}
__device__ __forceinline__ void cp_async16(uint32_t saddr, const void* gaddr) {
    asm volatile("cp.async.ca.shared.global [%0], [%1], 16;"
                 :: "r"(saddr), "l"(gaddr));
}
__device__ __forceinline__ void cp_commit() {
    asm volatile("cp.async.commit_group;");
}
__device__ __forceinline__ void cp_wait0() {
    asm volatile("cp.async.wait_group 0;");
}
__device__ __forceinline__ uint32_t smem_u32(const void* p) {
    uint32_t a;
    asm("{ .reg .u64 t; cvta.to.shared.u64 t, %1; cvt.u32.u64 %0, t; }"
        : "=r"(a) : "l"(p));
    return a;
}

// ---------------------------------------------------------------------------
// Self-detecting edge-index conversion (int64 vs int32), clamped.
__global__ void convert_idx_auto(const int* __restrict__ raw) {
    const unsigned int* w = (const unsigned int*)raw;
    unsigned int acc = 0;
#pragma unroll
    for (int i = 0; i < 16; i++) acc |= w[2 * i + 1];
    const bool is64 = (acc == 0u);

    int e = blockIdx.x * blockDim.x + threadIdx.x;
    if (e >= N_EDGES) return;
    int s, d;
    if (is64) { s = raw[2 * e]; d = raw[2 * (N_EDGES + e)]; }
    else      { s = raw[e];     d = raw[N_EDGES + e]; }
    g_src[e] = min(max(s, 0), N_NODES - 1);
    g_dst[e] = min(max(d, 0), N_NODES - 1);
}

// ---------------------------------------------------------------------------
// prep: blocks [0,256): quantize W2 row b -> int8 hi/lo + scale.
//       blocks [256,506): zero layer output (p==nullptr -> g_H).
//       blocks [506,631): per-node row maxes of C and B (one warp per node).
__global__ void prep_kernel(const float* __restrict__ W2, float4* __restrict__ p) {
    __shared__ float red[256];
    int b = blockIdx.x;
    int tid = threadIdx.x;
    if (b < 256) {
        float w = W2[b * 256 + tid];
        red[tid] = fabsf(w);
        __syncthreads();
#pragma unroll
        for (int o = 128; o > 0; o >>= 1) {
            if (tid < o) red[tid] = fmaxf(red[tid], red[tid + o]);
            __syncthreads();
        }
        float sw = fmaxf(red[0] * (1.f / 127.f), 1e-30f);
        float qf = rintf(w / sw);
        qf = fminf(fmaxf(qf, -127.f), 127.f);
        float r = w - qf * sw;
        float lf = rintf(r * (128.f / sw));
        lf = fminf(fmaxf(lf, -127.f), 127.f);
        g_Wqh[b * 256 + tid] = (char)(int)qf;
        g_Wql[b * 256 + tid] = (char)(int)lf;
        if (tid == 0) g_sw[b] = sw;
    } else if (b < 506) {
        float4* dst = p ? p : (float4*)g_H;
        int i = (b - 256) * 256 + tid;
        if (i < N_NODES * HIDDEN / 4)
            dst[i] = make_float4(0.f, 0.f, 0.f, 0.f);
    } else {
        int wid = tid >> 5, lane = tid & 31;
        int node = (b - 506) * 8 + wid;
        if (node < N_NODES) {
            float mc = -1e30f, mb = -1e30f;
#pragma unroll
            for (int i = 0; i < 8; i++) {
                mc = fmaxf(mc, g_C[node * 256 + i * 32 + lane]);
                mb = fmaxf(mb, g_B[node * 256 + i * 32 + lane]);
            }
#pragma unroll
            for (int o = 16; o > 0; o >>= 1) {
                mc = fmaxf(mc, __shfl_xor_sync(0xffffffffu, mc, o));
                mb = fmaxf(mb, __shfl_xor_sync(0xffffffffu, mb, o));
            }
            if (lane == 0) { g_mC[node] = mc; g_mB[node] = mb; }
        }
    }
}

// ---------------------------------------------------------------------------
// Node GEMM: C = A - B + b1, B = H @ W1b^T  (fp32, tiny: 1000x256)
template <int DIN>
__global__ __launch_bounds__(256) void node_gemm(
    const float* __restrict__ Hin, const float* __restrict__ W1,
    const float* __restrict__ b1)
{
    const float* H = Hin ? Hin : g_H;
    __shared__ float Hs[16][DIN];
    const int tid = threadIdx.x;
    const int n_base = blockIdx.x * 16;

    const int nvec = 16 * DIN / 4;
    for (int i = tid; i < nvec; i += 256) {
        int row = i / (DIN / 4);
        int c4 = i % (DIN / 4);
        int n = n_base + row;
        float4 v = make_float4(0.f, 0.f, 0.f, 0.f);
        if (n < N_NODES) v = ((const float4*)(H + (size_t)n * DIN))[c4];
        ((float4*)&Hs[row][0])[c4] = v;
    }
    __syncthreads();

    const int o = blockIdx.y * 128 + (tid & 127);
    const int ng = tid >> 7;

    float accA[8], accB[8];
#pragma unroll
    for (int j = 0; j < 8; j++) { accA[j] = 0.f; accB[j] = 0.f; }

    const float4* wA4 = (const float4*)(W1 + (size_t)o * 2 * DIN);
    const float4* wB4 = (const float4*)(W1 + (size_t)o * 2 * DIN + DIN);

    for (int k4 = 0; k4 < DIN / 4; k4++) {
        float4 wa = wA4[k4];
        float4 wb = wB4[k4];
        int kk = k4 * 4;
#pragma unroll
        for (int j = 0; j < 8; j++) {
            float h0 = Hs[ng * 8 + j][kk + 0];
            float h1 = Hs[ng * 8 + j][kk + 1];
            float h2 = Hs[ng * 8 + j][kk + 2];
            float h3 = Hs[ng * 8 + j][kk + 3];
            accA[j] += h0 * wa.x + h1 * wa.y + h2 * wa.z + h3 * wa.w;
            accB[j] += h0 * wb.x + h1 * wb.y + h2 * wb.z + h3 * wb.w;
        }
    }

    float bb = b1[o];
#pragma unroll
    for (int j = 0; j < 8; j++) {
        int n = n_base + ng * 8 + j;
        if (n < N_NODES) {
            g_B[n * HIDDEN + o] = accB[j];
            g_C[n * HIDDEN + o] = accA[j] - accB[j] + bb;
        }
    }
}

// ---------------------------------------------------------------------------
// INT8 fused edge kernel: TM=64 edges x TN=128 cols, 256 threads, 2 CTAs/SM.
// z ~ s*(qhi + qlo/128), w ~ sw*(phi + plo/128); 3 IMMA k32 passes:
//   accHi += qhi*phi ; accMid += qhi*plo + qlo*phi  (shared scale /128)
// D = s*sw*(accHi + accMid/128). K=256 in 8 chunks of 32, double-buffered.
// Epilogue: +bias, clamp>=0, int atomicMax scatter (out pre-zeroed).

#define TM 64
#define TN 128
#define SK8 48   // padded byte stride per k-row (32 data + 16 pad, conflict-free)

#define A_ST (TM * SK8)                 // 3072
#define B_ST (TN * SK8)                 // 6144
#define OFF_AHI(b) ((b) * A_ST)
#define OFF_ALO(b) (2 * A_ST + (b) * A_ST)
#define OFF_BHI(b) (4 * A_ST + (b) * B_ST)
#define OFF_BLO(b) (4 * A_ST + 2 * B_ST + (b) * B_ST)
#define OFF_DST  (4 * A_ST + 4 * B_ST)  // 36864
#define OFF_SRC  (OFF_DST + 256)
#define OFF_SZ   (OFF_DST + 512)
#define OFF_SZI  (OFF_DST + 768)
#define OFF_SW   (OFF_DST + 1024)
#define OFF_B2   (OFF_DST + 1536)
#define SM_TOTAL (OFF_DST + 2048)       // 38912 (static smem)

__global__ __launch_bounds__(256, 2) void edge_imma_kernel(
    const float* __restrict__ b2, float* __restrict__ outp)
{
    __shared__ __align__(16) char smem[SM_TOTAL];
    float* out = outp ? outp : g_H;
    const int tid = threadIdx.x;
    const int wid = tid >> 5;
    const int lane = tid & 31;
    const int e0 = blockIdx.x * TM;
    const int n0 = blockIdx.y * TN;

    int* dstS = (int*)(smem + OFF_DST);
    int* srcS = (int*)(smem + OFF_SRC);
    float* szS = (float*)(smem + OFF_SZ);
    float* sziS = (float*)(smem + OFF_SZI);
    float* swS = (float*)(smem + OFF_SW);
    float* b2s = (float*)(smem + OFF_B2);

    if (tid < TM) {
        int s = g_src[e0 + tid];
        int d = g_dst[e0 + tid];
        srcS[tid] = s;
        dstS[tid] = d;
        float bound = fmaxf(g_mC[d] + g_mB[s], 1e-12f);
        szS[tid] = bound * (1.f / 127.f);
        sziS[tid] = 127.f / bound;
    }
    if (tid < TN) {
        swS[tid] = g_sw[n0 + tid];
        b2s[tid] = b2[n0 + tid];
    }
    __syncthreads();

    const int wm = (wid >> 2) * 32;  // warp M offset (0 or 32)
    const int wn = (wid & 3) * 32;   // warp N offset (0..96)

    int accHi[2][4][4], accMid[2][4][4];
#pragma unroll
    for (int i = 0; i < 2; i++)
#pragma unroll
        for (int j = 0; j < 4; j++)
#pragma unroll
            for (int r = 0; r < 4; r++) { accHi[i][j][r] = 0; accMid[i][j][r] = 0; }

    const uint32_t sb = smem_u32(smem);

    // ---- loaders ----
    auto issue_W = [&](int buf, int kt) {
        // 512 tasks: row(128) x half(2) x slab(2)
#pragma unroll
        for (int i = 0; i < 2; i++) {
            int id = tid + i * 256;
            int row = id & 127;
            int comp = id >> 7;            // 0..3
            int half = comp & 1;
            int slab = comp >> 1;          // 0=hi 1=lo
            uint32_t so = (slab ? OFF_BLO(buf) : OFF_BHI(buf)) + row * SK8 + half * 16;
            const char* g = slab ? g_Wql : g_Wqh;
            cp_async16(sb + so, g + (n0 + row) * HIDDEN + kt + half * 16);
        }
        cp_commit();
    };
    auto ldg_Z = [&](int t, int kt, float4& cz, float4& bz) {
        int id = tid + t * 256;            // 0..511
        int row = id >> 3;                 // 0..63
        int k4 = (id & 7) * 4;
        cz = *(const float4*)&g_C[dstS[row] * HIDDEN + kt + k4];
        bz = *(const float4*)&g_B[srcS[row] * HIDDEN + kt + k4];
    };
    auto sts_Z = [&](int t, int buf, const float4& cz, const float4& bz) {
        int id = tid + t * 256;
        int row = id >> 3;
        int k4 = (id & 7) * 4;
        float sz = szS[row], szi = sziS[row];
        float zv[4] = { fmaxf(cz.x + bz.x, 0.f), fmaxf(cz.y + bz.y, 0.f),
                        fmaxf(cz.z + bz.z, 0.f), fmaxf(cz.w + bz.w, 0.f) };
        uint32_t hp = 0, lp = 0;
#pragma unroll
        for (int j = 0; j < 4; j++) {
            float qf = rintf(zv[j] * szi);
            int qh = (int)qf;
            float r = zv[j] - qf * sz;
            int ql = (int)rintf(r * szi * 128.f);
            hp |= (uint32_t)(qh & 255) << (j * 8);
            lp |= (uint32_t)(ql & 255) << (j * 8);
        }
        *(uint32_t*)(smem + OFF_AHI(buf) + row * SK8 + k4) = hp;
        *(uint32_t*)(smem + OFF_ALO(buf) + row * SK8 + k4) = lp;
    };
    auto ld_a = [&](uint32_t* a, int offBase, int mt) {
        int base = offBase + (wm + mt * 16 + (lane >> 2)) * SK8 + (lane & 3) * 4;
        a[0] = *(const uint32_t*)(smem + base);
        a[1] = *(const uint32_t*)(smem + base + 8 * SK8);
        a[2] = *(const uint32_t*)(smem + base + 16);
        a[3] = *(const uint32_t*)(smem + base + 8 * SK8 + 16);
    };
    auto ld_b = [&](uint32_t* bb, int offBase, int nt) {
        int base = offBase + (wn + nt * 8 + (lane >> 2)) * SK8 + (lane & 3) * 4;
        bb[0] = *(const uint32_t*)(smem + base);
        bb[1] = *(const uint32_t*)(smem + base + 16);
    };

    // ---- prologue: chunk 0 into buf 0 ----
    {
        issue_W(0, 0);
        float4 cz0, bz0, cz1, bz1;
        ldg_Z(0, 0, cz0, bz0);
        ldg_Z(1, 0, cz1, bz1);
        sts_Z(0, 0, cz0, bz0);
        sts_Z(1, 0, cz1, bz1);
        cp_wait0();
        __syncthreads();
    }

    // ---- main loop over 8 chunks of k32 ----
    for (int c = 0; c < 8; c++) {
        const int buf = c & 1;
        const int ktn = (c + 1) * 32;
        float4 cz0, bz0, cz1, bz1;
        if (c < 7) {
            issue_W(buf ^ 1, ktn);
            ldg_Z(0, ktn, cz0, bz0);
        }
        uint32_t ahi[2][4], bhi[4][2];
#pragma unroll
        for (int mt = 0; mt < 2; mt++) ld_a(ahi[mt], OFF_AHI(buf), mt);
#pragma unroll
        for (int nt = 0; nt < 4; nt++) ld_b(bhi[nt], OFF_BHI(buf), nt);
        // pass 1: hi*hi -> accHi (8 independent MMAs)
#pragma unroll
        for (int nt = 0; nt < 4; nt++)
#pragma unroll
            for (int mt = 0; mt < 2; mt++)
                mma_s8(accHi[mt][nt], ahi[mt], bhi[nt]);
        if (c < 7) {
            sts_Z(0, buf ^ 1, cz0, bz0);
            ldg_Z(1, ktn, cz1, bz1);
        }
        // pass 2: hi*lo -> accMid
        {
            uint32_t blo[4][2];
#pragma unroll
            for (int nt = 0; nt < 4; nt++) ld_b(blo[nt], OFF_BLO(buf), nt);
#pragma unroll
            for (int nt = 0; nt < 4; nt++)
#pragma unroll
                for (int mt = 0; mt < 2; mt++)
                    mma_s8(accMid[mt][nt], ahi[mt], blo[nt]);
        }
        if (c < 7) sts_Z(1, buf ^ 1, cz1, bz1);
        // pass 3: lo*hi -> accMid
        {
            uint32_t alo[2][4];
#pragma unroll
            for (int mt = 0; mt < 2; mt++) ld_a(alo[mt], OFF_ALO(buf), mt);
#pragma unroll
            for (int nt = 0; nt < 4; nt++)
#pragma unroll
                for (int mt = 0; mt < 2; mt++)
                    mma_s8(accMid[mt][nt], alo[mt], bhi[nt]);
        }
        if (c < 7) cp_wait0();
        __syncthreads();
    }

    // ---- epilogue: dequant, bias, clamp, int atomicMax scatter ----
    int* oi = (int*)out;
    const int gr = lane >> 2;
    const int gc = (lane & 3) * 2;
#pragma unroll
    for (int mt = 0; mt < 2; mt++) {
#pragma unroll
        for (int half = 0; half < 2; half++) {
            int row = wm + mt * 16 + gr + half * 8;
            int d = dstS[row];
            float szr = szS[row];
            int base = d * HIDDEN + n0;
#pragma unroll
            for (int nt = 0; nt < 4; nt++) {
                int col = wn + nt * 8 + gc;
                float sc0 = szr * swS[col];
                float sc1 = szr * swS[col + 1];
                float v0 = ((float)accHi[mt][nt][half * 2 + 0] +
                            (float)accMid[mt][nt][half * 2 + 0] * 0.0078125f) * sc0
                           + b2s[col];
                float v1 = ((float)accHi[mt][nt][half * 2 + 1] +
                            (float)accMid[mt][nt][half * 2 + 1] * 0.0078125f) * sc1
                           + b2s[col + 1];
                if (v0 > 0.f) atomicMax(&oi[base + col], __float_as_int(v0));
                if (v1 > 0.f) atomicMax(&oi[base + col + 1], __float_as_int(v1));
            }
        }
    }
}

// ---------------------------------------------------------------------------
extern "C" void kernel_launch(void* const* d_in, const int* in_sizes, int n_in,
                              void* d_out, int out_size) {
    const float* x = (const float*)d_in[0];
    const int* ei_raw = (const int*)d_in[1];

    // launch 0
    convert_idx_auto<<<(N_EDGES + 255) / 256, 256>>>(ei_raw);

    for (int l = 0; l < 5; l++) {
        const float* W1 = (const float*)d_in[2 + 4 * l];
        const float* b1 = (const float*)d_in[3 + 4 * l];
        const float* W2 = (const float*)d_in[4 + 4 * l];
        const float* b2 = (const float*)d_in[5 + 4 * l];

        // launches 1,2,3 in layer 0 -> edge at ncu's captured index 3
        if (l == 0)
            node_gemm<IN_DIM><<<dim3(63, 2), 256>>>(x, W1, b1);
        else
            node_gemm<HIDDEN><<<dim3(63, 2), 256>>>(nullptr, W1, b1);

        float* outl = (l == 4) ? (float*)d_out : nullptr;
        prep_kernel<<<631, 256>>>(W2, (float4*)outl);

        edge_imma_kernel<<<dim3(N_EDGES / TM, HIDDEN / TN), 256>>>(b2, outl);
    }
}

// round 13
// speedup vs baseline: 1.0207x; 1.0207x over previous
#include <cuda_runtime.h>
#include <cuda_bf16.h>
#include <cstdint>

#define N_NODES 1000
#define HIDDEN  256
#define IN_DIM  128
#define N_EDGES 64000

// Scratch (device globals: no allocation allowed)
__device__ float g_C[N_NODES * HIDDEN];    // A - B + b1   (per node)
__device__ float g_B[N_NODES * HIDDEN];    // B = X @ W1b^T (per node)
__device__ float g_H[N_NODES * HIDDEN];    // node features between layers
__device__ __nv_bfloat16 g_Whi[HIDDEN * HIDDEN];  // W2 hi (bf16, [n][k] k-major)
__device__ __nv_bfloat16 g_Wlo[HIDDEN * HIDDEN];  // W2 lo residual
__device__ int   g_src[N_EDGES];
__device__ int   g_dst[N_EDGES];

// ---------------------------------------------------------------------------
__device__ __forceinline__ uint32_t smem_u32(const void* p) {
    uint32_t a;
    asm("{ .reg .u64 t; cvta.to.shared.u64 t, %1; cvt.u32.u64 %0, t; }"
        : "=r"(a) : "l"(p));
    return a;
}
__device__ __forceinline__ void ldmatrix_x4(uint32_t* r, uint32_t addr) {
    asm volatile(
        "ldmatrix.sync.aligned.m8n8.x4.shared.b16 {%0, %1, %2, %3}, [%4];"
        : "=r"(r[0]), "=r"(r[1]), "=r"(r[2]), "=r"(r[3]) : "r"(addr));
}
__device__ __forceinline__ void mma_bf16(float* d, const uint32_t* a,
                                         const uint32_t* b) {
    asm volatile(
        "mma.sync.aligned.m16n8k16.row.col.f32.bf16.bf16.f32 "
        "{%0, %1, %2, %3}, {%4, %5, %6, %7}, {%8, %9}, {%0, %1, %2, %3};"
        : "+f"(d[0]), "+f"(d[1]), "+f"(d[2]), "+f"(d[3])
        : "r"(a[0]), "r"(a[1]), "r"(a[2]), "r"(a[3]), "r"(b[0]), "r"(b[1]));
}
__device__ __forceinline__ void cp_async16(uint32_t saddr, const void* gaddr) {
    asm volatile("cp.async.ca.shared.global [%0], [%1], 16;"
                 :: "r"(saddr), "l"(gaddr));
}
__device__ __forceinline__ void cp_commit() {
    asm volatile("cp.async.commit_group;");
}
__device__ __forceinline__ void cp_wait0() {
    asm volatile("cp.async.wait_group 0;");
}
__device__ __forceinline__ void bar_sync(int id) {
    asm volatile("bar.sync %0, 384;" :: "r"(id) : "memory");
}
__device__ __forceinline__ void bar_arrive(int id) {
    asm volatile("bar.arrive %0, 384;" :: "r"(id) : "memory");
}

// ---------------------------------------------------------------------------
// Self-detecting edge-index conversion (int64 vs int32), clamped.
__global__ void convert_idx_auto(const int* __restrict__ raw) {
    const unsigned int* w = (const unsigned int*)raw;
    unsigned int acc = 0;
#pragma unroll
    for (int i = 0; i < 16; i++) acc |= w[2 * i + 1];
    const bool is64 = (acc == 0u);

    int e = blockIdx.x * blockDim.x + threadIdx.x;
    if (e >= N_EDGES) return;
    int s, d;
    if (is64) { s = raw[2 * e]; d = raw[2 * (N_EDGES + e)]; }
    else      { s = raw[e];     d = raw[N_EDGES + e]; }
    g_src[e] = min(max(s, 0), N_NODES - 1);
    g_dst[e] = min(max(d, 0), N_NODES - 1);
}

// ---------------------------------------------------------------------------
// prep: blocks [0,256) convert W2 fp32 -> (hi,lo) bf16; blocks [256,506)
// zero the layer output (p == nullptr -> g_H).
__global__ void prep_kernel(const float* __restrict__ W2, float4* __restrict__ p) {
    int b = blockIdx.x;
    if (b < 256) {
        int i = b * 256 + threadIdx.x;
        float w = W2[i];
        __nv_bfloat16 hi = __float2bfloat16(w);
        __nv_bfloat16 lo = __float2bfloat16(w - __bfloat162float(hi));
        g_Whi[i] = hi;
        g_Wlo[i] = lo;
    } else {
        float4* dst = p ? p : (float4*)g_H;
        int i = (b - 256) * 256 + threadIdx.x;
        if (i < N_NODES * HIDDEN / 4)
            dst[i] = make_float4(0.f, 0.f, 0.f, 0.f);
    }
}

// ---------------------------------------------------------------------------
// Node GEMM: C = A - B + b1, B = H @ W1b^T  (fp32, tiny: 1000x256)
template <int DIN>
__global__ __launch_bounds__(256) void node_gemm(
    const float* __restrict__ Hin, const float* __restrict__ W1,
    const float* __restrict__ b1)
{
    const float* H = Hin ? Hin : g_H;
    __shared__ float Hs[16][DIN];
    const int tid = threadIdx.x;
    const int n_base = blockIdx.x * 16;

    const int nvec = 16 * DIN / 4;
    for (int i = tid; i < nvec; i += 256) {
        int row = i / (DIN / 4);
        int c4 = i % (DIN / 4);
        int n = n_base + row;
        float4 v = make_float4(0.f, 0.f, 0.f, 0.f);
        if (n < N_NODES) v = ((const float4*)(H + (size_t)n * DIN))[c4];
        ((float4*)&Hs[row][0])[c4] = v;
    }
    __syncthreads();

    const int o = blockIdx.y * 128 + (tid & 127);
    const int ng = tid >> 7;

    float accA[8], accB[8];
#pragma unroll
    for (int j = 0; j < 8; j++) { accA[j] = 0.f; accB[j] = 0.f; }

    const float4* wA4 = (const float4*)(W1 + (size_t)o * 2 * DIN);
    const float4* wB4 = (const float4*)(W1 + (size_t)o * 2 * DIN + DIN);

    for (int k4 = 0; k4 < DIN / 4; k4++) {
        float4 wa = wA4[k4];
        float4 wb = wB4[k4];
        int kk = k4 * 4;
#pragma unroll
        for (int j = 0; j < 8; j++) {
            float h0 = Hs[ng * 8 + j][kk + 0];
            float h1 = Hs[ng * 8 + j][kk + 1];
            float h2 = Hs[ng * 8 + j][kk + 2];
            float h3 = Hs[ng * 8 + j][kk + 3];
            accA[j] += h0 * wa.x + h1 * wa.y + h2 * wa.z + h3 * wa.w;
            accB[j] += h0 * wb.x + h1 * wb.y + h2 * wb.z + h3 * wb.w;
        }
    }

    float bb = b1[o];
#pragma unroll
    for (int j = 0; j < 8; j++) {
        int n = n_base + ng * 8 + j;
        if (n < N_NODES) {
            g_B[n * HIDDEN + o] = accB[j];
            g_C[n * HIDDEN + o] = accA[j] - accB[j] + bb;
        }
    }
}

// ---------------------------------------------------------------------------
// Warp-specialized HMMA edge kernel: 384 threads/CTA.
//   warps 0-7 : consumers — tile 128 edges x 128 cols (32x64 each), 3-pass
//               split-bf16 MMA (validated R11 fragment math).
//   warps 8-11: producers — Z gather + split-convert + STS, W cp.async,
//               filling a 3-stage smem ring.
// Named-barrier handshake: full[s]=1+s (producers arrive, consumers sync),
// empty[s]=4+s (consumers arrive, producers sync when wrapping).
// Epilogue: +bias, clamp>=0, int atomicMax scatter (out pre-zeroed).

#define TM 128
#define TN 128
#define TK 32
#define SK 40   // padded bf16 k-stride
#define NSTAGE 3

#define A_SZ 10240                 // TM * SK * 2
#define B_SZ 10240                 // TN * SK * 2
#define STAGE_SZ (2 * A_SZ + 2 * B_SZ)   // 40960
#define S_AHI(s) ((s) * STAGE_SZ)
#define S_ALO(s) ((s) * STAGE_SZ + A_SZ)
#define S_BHI(s) ((s) * STAGE_SZ + 2 * A_SZ)
#define S_BLO(s) ((s) * STAGE_SZ + 2 * A_SZ + B_SZ)
#define OFF_DST (NSTAGE * STAGE_SZ)      // 122880
#define OFF_SRC (OFF_DST + 512)
#define OFF_B2  (OFF_DST + 1024)
#define SM_TOTAL (OFF_DST + 1536)        // 124416

__global__ __launch_bounds__(384) void edge_ws_kernel(
    const float* __restrict__ b2, float* __restrict__ outp)
{
    extern __shared__ char smem[];
    float* out = outp ? outp : g_H;
    const uint32_t sb = smem_u32(smem);
    const int tid = threadIdx.x;
    const int wid = tid >> 5;
    const int lane = tid & 31;
    const int e0 = blockIdx.x * TM;
    const int n0 = blockIdx.y * TN;

    int* dstS = (int*)(smem + OFF_DST);
    int* srcS = (int*)(smem + OFF_SRC);
    float* b2s = (float*)(smem + OFF_B2);

    if (tid < TM) {
        srcS[tid] = g_src[e0 + tid];
        dstS[tid] = g_dst[e0 + tid];
        b2s[tid] = b2[n0 + tid];
    }
    __syncthreads();

    if (wid < 8) {
        // ================= CONSUMERS =================
        const int wm = (wid >> 1) * 32;  // 0..96
        const int wn = (wid & 1) * 64;   // 0 or 64

        float acc[2][8][4];
#pragma unroll
        for (int i = 0; i < 2; i++)
#pragma unroll
            for (int j = 0; j < 8; j++)
#pragma unroll
                for (int r = 0; r < 4; r++) acc[i][j][r] = 0.f;

        const int a_row = lane & 15;
        const int a_kof = (lane >> 4) << 3;
        const int b_row = ((lane >> 4) << 3) + (lane & 7);
        const int b_kof = ((lane >> 3) & 1) << 3;

        auto mma_ks = [&](int st, int ks) {
            uint32_t ahi[2][4], bhi[4][4];
#pragma unroll
            for (int mt = 0; mt < 2; mt++) {
                uint32_t ao = (uint32_t)((wm + mt * 16 + a_row) * SK + ks + a_kof) * 2;
                ldmatrix_x4(ahi[mt], sb + S_AHI(st) + ao);
            }
#pragma unroll
            for (int nt = 0; nt < 4; nt++) {
                uint32_t bo = (uint32_t)((wn + nt * 16 + b_row) * SK + ks + b_kof) * 2;
                ldmatrix_x4(bhi[nt], sb + S_BHI(st) + bo);
            }
            // pass 1: hi*hi
#pragma unroll
            for (int nt = 0; nt < 4; nt++)
#pragma unroll
                for (int mt = 0; mt < 2; mt++) {
                    mma_bf16(acc[mt][nt * 2 + 0], ahi[mt], &bhi[nt][0]);
                    mma_bf16(acc[mt][nt * 2 + 1], ahi[mt], &bhi[nt][2]);
                }
            // pass 2: hi*lo
            {
                uint32_t blo[4][4];
#pragma unroll
                for (int nt = 0; nt < 4; nt++) {
                    uint32_t bo = (uint32_t)((wn + nt * 16 + b_row) * SK + ks + b_kof) * 2;
                    ldmatrix_x4(blo[nt], sb + S_BLO(st) + bo);
                }
#pragma unroll
                for (int nt = 0; nt < 4; nt++)
#pragma unroll
                    for (int mt = 0; mt < 2; mt++) {
                        mma_bf16(acc[mt][nt * 2 + 0], ahi[mt], &blo[nt][0]);
                        mma_bf16(acc[mt][nt * 2 + 1], ahi[mt], &blo[nt][2]);
                    }
            }
            // pass 3: lo*hi
            {
                uint32_t alo[2][4];
#pragma unroll
                for (int mt = 0; mt < 2; mt++) {
                    uint32_t ao = (uint32_t)((wm + mt * 16 + a_row) * SK + ks + a_kof) * 2;
                    ldmatrix_x4(alo[mt], sb + S_ALO(st) + ao);
                }
#pragma unroll
                for (int nt = 0; nt < 4; nt++)
#pragma unroll
                    for (int mt = 0; mt < 2; mt++) {
                        mma_bf16(acc[mt][nt * 2 + 0], alo[mt], &bhi[nt][0]);
                        mma_bf16(acc[mt][nt * 2 + 1], alo[mt], &bhi[nt][2]);
                    }
            }
        };

        for (int c = 0; c < 8; c++) {
            int st = c % NSTAGE;
            bar_sync(1 + st);          // wait full
            mma_ks(st, 0);
            mma_ks(st, 16);
            bar_arrive(4 + st);        // release empty
        }

        // epilogue: bias, clamp, int atomicMax scatter (nonneg floats)
        int* oi = (int*)out;
        const int gr = lane >> 2;
        const int gc = (lane & 3) * 2;
#pragma unroll
        for (int mt = 0; mt < 2; mt++) {
#pragma unroll
            for (int half = 0; half < 2; half++) {
                int row = wm + mt * 16 + gr + half * 8;
                int d = dstS[row];
                int base = d * HIDDEN + n0;
#pragma unroll
                for (int ns = 0; ns < 8; ns++) {
                    int col = wn + ns * 8 + gc;
                    float v0 = acc[mt][ns][half * 2 + 0] + b2s[col];
                    float v1 = acc[mt][ns][half * 2 + 1] + b2s[col + 1];
                    if (v0 > 0.f) atomicMax(&oi[base + col], __float_as_int(v0));
                    if (v1 > 0.f) atomicMax(&oi[base + col + 1], __float_as_int(v1));
                }
            }
        }
    } else {
        // ================= PRODUCERS =================
        const int ptid = tid - 256;  // 0..127

        for (int cp = 0; cp < 8; cp++) {
            int st = cp % NSTAGE;
            int kt = cp * TK;
            if (cp >= NSTAGE) bar_sync(4 + st);  // wait empty

            // W slabs: 128 n-rows x 64B per slab, 2 slabs -> 8 cp.async/thread
#pragma unroll
            for (int i = 0; i < 8; i++) {
                int id = ptid + i * 128;
                int row = id & 127;
                int t = id >> 7;        // 0..7
                int slab = t >> 2;      // 0=hi 1=lo
                int q = t & 3;          // 16B quarter
                uint32_t doff = (slab ? S_BLO(st) : S_BHI(st)) + row * (SK * 2) + q * 16;
                const __nv_bfloat16* g = slab ? g_Wlo : g_Whi;
                cp_async16(sb + doff, g + (n0 + row) * HIDDEN + kt + q * 8);
            }
            cp_commit();

            // Z gather + split-convert: 128 rows x 8 float4-slots -> 8/thread
#pragma unroll
            for (int i = 0; i < 8; i++) {
                int id = ptid + i * 128;
                int row = id >> 3;
                int k4 = (id & 7) * 4;
                const float4 cz = *(const float4*)&g_C[dstS[row] * HIDDEN + kt + k4];
                const float4 bz = *(const float4*)&g_B[srcS[row] * HIDDEN + kt + k4];
                float2 z01 = make_float2(fmaxf(cz.x + bz.x, 0.f), fmaxf(cz.y + bz.y, 0.f));
                float2 z23 = make_float2(fmaxf(cz.z + bz.z, 0.f), fmaxf(cz.w + bz.w, 0.f));
                __nv_bfloat162 h01 = __float22bfloat162_rn(z01);
                __nv_bfloat162 h23 = __float22bfloat162_rn(z23);
                float2 hf01 = __bfloat1622float2(h01);
                float2 hf23 = __bfloat1622float2(h23);
                __nv_bfloat162 l01 = __float22bfloat162_rn(
                    make_float2(z01.x - hf01.x, z01.y - hf01.y));
                __nv_bfloat162 l23 = __float22bfloat162_rn(
                    make_float2(z23.x - hf23.x, z23.y - hf23.y));
                uint32_t eo = (uint32_t)(row * SK + k4) * 2;
                *(uint2*)(smem + S_AHI(st) + eo) =
                    make_uint2(*(uint32_t*)&h01, *(uint32_t*)&h23);
                *(uint2*)(smem + S_ALO(st) + eo) =
                    make_uint2(*(uint32_t*)&l01, *(uint32_t*)&l23);
            }

            cp_wait0();
            __threadfence_block();
            bar_arrive(1 + st);        // publish full
        }
    }
}

// ---------------------------------------------------------------------------
extern "C" void kernel_launch(void* const* d_in, const int* in_sizes, int n_in,
                              void* d_out, int out_size) {
    const float* x = (const float*)d_in[0];
    const int* ei_raw = (const int*)d_in[1];

    static bool attr_set = false;
    if (!attr_set) {
        cudaFuncSetAttribute(edge_ws_kernel,
                             cudaFuncAttributeMaxDynamicSharedMemorySize,
                             SM_TOTAL);
        attr_set = true;
    }

    // launch 0
    convert_idx_auto<<<(N_EDGES + 255) / 256, 256>>>(ei_raw);

    for (int l = 0; l < 5; l++) {
        const float* W1 = (const float*)d_in[2 + 4 * l];
        const float* b1 = (const float*)d_in[3 + 4 * l];
        const float* W2 = (const float*)d_in[4 + 4 * l];
        const float* b2 = (const float*)d_in[5 + 4 * l];

        // launches 1,2,3 in layer 0 -> edge at ncu's captured index 3
        if (l == 0)
            node_gemm<IN_DIM><<<dim3(63, 2), 256>>>(x, W1, b1);
        else
            node_gemm<HIDDEN><<<dim3(63, 2), 256>>>(nullptr, W1, b1);

        float* outl = (l == 4) ? (float*)d_out : nullptr;
        prep_kernel<<<506, 256>>>(W2, (float4*)outl);

        edge_ws_kernel<<<dim3(N_EDGES / TM, HIDDEN / TN), 384, SM_TOTAL>>>(
            b2, outl);
    }
}

// round 15
// speedup vs baseline: 1.0780x; 1.0562x over previous
#include <cuda_runtime.h>
#include <cuda_fp16.h>
#include <cstdint>

#define N_NODES 1000
#define HIDDEN  256
#define IN_DIM  128
#define N_EDGES 64000

// Scratch (device globals: no allocation allowed)
__device__ float g_C[N_NODES * HIDDEN];    // A - B + b1   (per node)
__device__ float g_B[N_NODES * HIDDEN];    // B = X @ W1b^T (per node)
__device__ float g_H0[N_NODES * HIDDEN];   // ping-pong node features
__device__ float g_H1[N_NODES * HIDDEN];
__device__ __half g_Wh[5 * HIDDEN * HIDDEN];  // W2 hi fp16, all 5 layers
__device__ __half g_Wl[5 * HIDDEN * HIDDEN];  // W2 lo fp16 residual
__device__ int   g_src[N_EDGES];
__device__ int   g_dst[N_EDGES];

// ---------------------------------------------------------------------------
__device__ __forceinline__ uint32_t smem_u32(const void* p) {
    uint32_t a;
    asm("{ .reg .u64 t; cvta.to.shared.u64 t, %1; cvt.u32.u64 %0, t; }"
        : "=r"(a) : "l"(p));
    return a;
}
__device__ __forceinline__ void ldmatrix_x4(uint32_t* r, uint32_t addr) {
    asm volatile(
        "ldmatrix.sync.aligned.m8n8.x4.shared.b16 {%0, %1, %2, %3}, [%4];"
        : "=r"(r[0]), "=r"(r[1]), "=r"(r[2]), "=r"(r[3]) : "r"(addr));
}
// fp16 inputs, fp32 accumulate (main pass)
__device__ __forceinline__ void mma_f32acc(float* d, const uint32_t* a,
                                           const uint32_t* b) {
    asm volatile(
        "mma.sync.aligned.m16n8k16.row.col.f32.f16.f16.f32 "
        "{%0, %1, %2, %3}, {%4, %5, %6, %7}, {%8, %9}, {%0, %1, %2, %3};"
        : "+f"(d[0]), "+f"(d[1]), "+f"(d[2]), "+f"(d[3])
        : "r"(a[0]), "r"(a[1]), "r"(a[2]), "r"(a[3]), "r"(b[0]), "r"(b[1]));
}
// fp16 inputs, fp16 accumulate (cross passes; hypothesized 2x rate)
__device__ __forceinline__ void mma_f16acc(uint32_t* d, const uint32_t* a,
                                           const uint32_t* b) {
    asm volatile(
        "mma.sync.aligned.m16n8k16.row.col.f16.f16.f16.f16 "
        "{%0, %1}, {%2, %3, %4, %5}, {%6, %7}, {%0, %1};"
        : "+r"(d[0]), "+r"(d[1])
        : "r"(a[0]), "r"(a[1]), "r"(a[2]), "r"(a[3]), "r"(b[0]), "r"(b[1]));
}
__device__ __forceinline__ void cp_async16(uint32_t saddr, const void* gaddr) {
    asm volatile("cp.async.ca.shared.global [%0], [%1], 16;"
                 :: "r"(saddr), "l"(gaddr));
}
__device__ __forceinline__ void cp_commit() {
    asm volatile("cp.async.commit_group;");
}
__device__ __forceinline__ void cp_wait0() {
    asm volatile("cp.async.wait_group 0;");
}

// ---------------------------------------------------------------------------
// Self-detecting edge-index conversion (int64 vs int32), clamped.
__global__ void convert_idx_auto(const int* __restrict__ raw) {
    const unsigned int* w = (const unsigned int*)raw;
    unsigned int acc = 0;
#pragma unroll
    for (int i = 0; i < 16; i++) acc |= w[2 * i + 1];
    const bool is64 = (acc == 0u);

    int e = blockIdx.x * blockDim.x + threadIdx.x;
    if (e >= N_EDGES) return;
    int s, d;
    if (is64) { s = raw[2 * e]; d = raw[2 * (N_EDGES + e)]; }
    else      { s = raw[e];     d = raw[N_EDGES + e]; }
    g_src[e] = min(max(s, 0), N_NODES - 1);
    g_dst[e] = min(max(d, 0), N_NODES - 1);
}

// ---------------------------------------------------------------------------
// One-time: split all 5 W2 into fp16 hi/lo; also zero g_H0 (layer-0 output).
__global__ void prep_w_all(const float* __restrict__ w0, const float* __restrict__ w1,
                           const float* __restrict__ w2, const float* __restrict__ w3,
                           const float* __restrict__ w4) {
    const float* ws[5] = {w0, w1, w2, w3, w4};
    int b = blockIdx.x;           // 0..1279
    int l = b >> 8;
    int i = (b & 255) * 256 + threadIdx.x;
    float w = ws[l][i];
    __half hi = __float2half_rn(w);
    __half lo = __float2half_rn(w - __half2float(hi));
    g_Wh[l * (HIDDEN * HIDDEN) + i] = hi;
    g_Wl[l * (HIDDEN * HIDDEN) + i] = lo;
    if (b < 250) {  // 250*256 = 64000 float4 = full g_H0
        ((float4*)g_H0)[b * 256 + threadIdx.x] =
            make_float4(0.f, 0.f, 0.f, 0.f);
    }
}

// ---------------------------------------------------------------------------
// Node GEMM: C = A - B + b1, B = H @ W1b^T  (fp32, tiny: 1000x256)
// in_sel: 0 -> x, 1 -> g_H0, 2 -> g_H1
template <int DIN>
__global__ __launch_bounds__(256) void node_gemm(
    const float* __restrict__ x, const float* __restrict__ W1,
    const float* __restrict__ b1, int in_sel)
{
    const float* H = (in_sel == 0) ? x : (in_sel == 1 ? g_H0 : g_H1);
    __shared__ float Hs[16][DIN];
    const int tid = threadIdx.x;
    const int n_base = blockIdx.x * 16;

    const int nvec = 16 * DIN / 4;
    for (int i = tid; i < nvec; i += 256) {
        int row = i / (DIN / 4);
        int c4 = i % (DIN / 4);
        int n = n_base + row;
        float4 v = make_float4(0.f, 0.f, 0.f, 0.f);
        if (n < N_NODES) v = ((const float4*)(H + (size_t)n * DIN))[c4];
        ((float4*)&Hs[row][0])[c4] = v;
    }
    __syncthreads();

    const int o = blockIdx.y * 128 + (tid & 127);
    const int ng = tid >> 7;

    float accA[8], accB[8];
#pragma unroll
    for (int j = 0; j < 8; j++) { accA[j] = 0.f; accB[j] = 0.f; }

    const float4* wA4 = (const float4*)(W1 + (size_t)o * 2 * DIN);
    const float4* wB4 = (const float4*)(W1 + (size_t)o * 2 * DIN + DIN);

    for (int k4 = 0; k4 < DIN / 4; k4++) {
        float4 wa = wA4[k4];
        float4 wb = wB4[k4];
        int kk = k4 * 4;
#pragma unroll
        for (int j = 0; j < 8; j++) {
            float h0 = Hs[ng * 8 + j][kk + 0];
            float h1 = Hs[ng * 8 + j][kk + 1];
            float h2 = Hs[ng * 8 + j][kk + 2];
            float h3 = Hs[ng * 8 + j][kk + 3];
            accA[j] += h0 * wa.x + h1 * wa.y + h2 * wa.z + h3 * wa.w;
            accB[j] += h0 * wb.x + h1 * wb.y + h2 * wb.z + h3 * wb.w;
        }
    }

    float bb = b1[o];
#pragma unroll
    for (int j = 0; j < 8; j++) {
        int n = n_base + ng * 8 + j;
        if (n < N_NODES) {
            g_B[n * HIDDEN + o] = accB[j];
            g_C[n * HIDDEN + o] = accA[j] - accB[j] + bb;
        }
    }
}

// ---------------------------------------------------------------------------
// HMMA fused edge kernel (fp16 split, R9 shape: 256 thr, 2 CTAs/SM,
// TM=128 x TN=128, warp tile 32x64, K=256 dbl-buffered chunks of 32):
//   pass 1: zh*wh -> fp32 acc ; passes 2+3: zh*wl, zl*wh -> shared fp16 acc.
// Also zeros the NEXT layer's output buffer (zero_sel), safe because that
// buffer is this layer's node-GEMM input, already consumed.
// out_sel/zero_sel: 0 none, 1 g_H0, 2 g_H1, 3 dout.

#define TM 128
#define TN 128
#define TK 32
#define SK 40   // padded fp16 k-stride

#define A_STAGE (TM * SK * 2)              // 10240
#define B_STAGE (TN * SK * 2)              // 10240
#define OFF_AHI 0
#define OFF_ALO (2 * A_STAGE)              // 20480
#define OFF_BHI (4 * A_STAGE)              // 40960
#define OFF_BLO (4 * A_STAGE + 2 * B_STAGE)// 61440
#define OFF_DST (4 * A_STAGE + 4 * B_STAGE)// 81920
#define OFF_SRC (OFF_DST + 512)
#define OFF_B2  (OFF_SRC + 512)
#define SM_TOTAL (OFF_B2 + 512)            // 83456

__global__ __launch_bounds__(256, 2) void edge_hmma_kernel(
    const float* __restrict__ b2, float* __restrict__ dout,
    int out_sel, int zero_sel, int loff)
{
    extern __shared__ char smem[];
    float* out = (out_sel == 3) ? dout : (out_sel == 1 ? g_H0 : g_H1);
    const uint32_t sb = smem_u32(smem);
    const int tid = threadIdx.x;
    const int wid = tid >> 5;
    const int lane = tid & 31;
    const int e0 = blockIdx.x * TM;
    const int n0 = blockIdx.y * TN;

    // zero next layer's output buffer: 1000 CTAs x 64 float4 = 64000
    if (zero_sel != 0 && tid < 64) {
        float4* zp = (zero_sel == 3) ? (float4*)dout
                                     : (zero_sel == 1 ? (float4*)g_H0
                                                      : (float4*)g_H1);
        int cta = blockIdx.x * 2 + blockIdx.y;
        zp[cta * 64 + tid] = make_float4(0.f, 0.f, 0.f, 0.f);
    }

    int* dstS = (int*)(smem + OFF_DST);
    int* srcS = (int*)(smem + OFF_SRC);
    float* b2s = (float*)(smem + OFF_B2);

    if (tid < TM) {
        srcS[tid] = g_src[e0 + tid];
        dstS[tid] = g_dst[e0 + tid];
    }
    if (tid < TN) b2s[tid] = b2[n0 + tid];
    __syncthreads();

    const int wm = (wid >> 1) * 32;  // warp M offset (0..96)
    const int wn = (wid & 1) * 64;   // warp N offset (0 or 64)

    float acc[2][8][4];
    uint32_t accC[2][8][2];          // fp16 cross accumulator
#pragma unroll
    for (int i = 0; i < 2; i++)
#pragma unroll
        for (int j = 0; j < 8; j++) {
#pragma unroll
            for (int r = 0; r < 4; r++) acc[i][j][r] = 0.f;
            accC[i][j][0] = 0u;
            accC[i][j][1] = 0u;
        }

    const int a_row = lane & 15;
    const int a_kof = (lane >> 4) << 3;
    const int b_row = ((lane >> 4) << 3) + (lane & 7);
    const int b_kof = ((lane >> 3) & 1) << 3;

    const __half* Whp = g_Wh + loff;
    const __half* Wlp = g_Wl + loff;

    auto issue_W = [&](int buf, int kt) {
#pragma unroll
        for (int i = 0; i < 2; i++) {
            int id = tid + i * 256;
            int row = id >> 2;
            int k8 = (id & 3) * 8;
            uint32_t so = (uint32_t)(row * SK + k8) * 2;
            cp_async16(sb + OFF_BHI + buf * B_STAGE + so,
                       Whp + (n0 + row) * HIDDEN + kt + k8);
            cp_async16(sb + OFF_BLO + buf * B_STAGE + so,
                       Wlp + (n0 + row) * HIDDEN + kt + k8);
        }
        cp_commit();
    };
    auto ldg_Z = [&](int h, int kt, float4& cz, float4& bz) {
        int id = tid + h * 256;
        int row = id >> 3;
        int k4 = (id & 7) * 4;
        cz = *(const float4*)&g_C[dstS[row] * HIDDEN + kt + k4];
        bz = *(const float4*)&g_B[srcS[row] * HIDDEN + kt + k4];
    };
    auto sts_Z = [&](int h, int buf, const float4& cz, const float4& bz) {
        int id = tid + h * 256;
        int row = id >> 3;
        int k4 = (id & 7) * 4;
        float z0 = fmaxf(cz.x + bz.x, 0.f), z1 = fmaxf(cz.y + bz.y, 0.f);
        float z2 = fmaxf(cz.z + bz.z, 0.f), z3 = fmaxf(cz.w + bz.w, 0.f);
        __half2 h01 = __floats2half2_rn(z0, z1);
        __half2 h23 = __floats2half2_rn(z2, z3);
        float2 f01 = __half22float2(h01);
        float2 f23 = __half22float2(h23);
        __half2 l01 = __floats2half2_rn(z0 - f01.x, z1 - f01.y);
        __half2 l23 = __floats2half2_rn(z2 - f23.x, z3 - f23.y);
        uint32_t eo = (uint32_t)(row * SK + k4) * 2;
        *(uint2*)(smem + OFF_AHI + buf * A_STAGE + eo) =
            make_uint2(*(uint32_t*)&h01, *(uint32_t*)&h23);
        *(uint2*)(smem + OFF_ALO + buf * A_STAGE + eo) =
            make_uint2(*(uint32_t*)&l01, *(uint32_t*)&l23);
    };
    auto mma_ks = [&](int buf, int ks) {
        uint32_t ahi[2][4], alo[2][4];
#pragma unroll
        for (int mt = 0; mt < 2; mt++) {
            uint32_t ao = (uint32_t)((wm + mt * 16 + a_row) * SK + ks + a_kof) * 2;
            ldmatrix_x4(ahi[mt], sb + OFF_AHI + buf * A_STAGE + ao);
            ldmatrix_x4(alo[mt], sb + OFF_ALO + buf * A_STAGE + ao);
        }
#pragma unroll
        for (int nt = 0; nt < 4; nt++) {
            uint32_t bhi[4];
            uint32_t bo = (uint32_t)((wn + nt * 16 + b_row) * SK + ks + b_kof) * 2;
            ldmatrix_x4(bhi, sb + OFF_BHI + buf * B_STAGE + bo);
#pragma unroll
            for (int mt = 0; mt < 2; mt++) {
                mma_f32acc(acc[mt][nt * 2 + 0], ahi[mt], &bhi[0]);
                mma_f32acc(acc[mt][nt * 2 + 1], ahi[mt], &bhi[2]);
                mma_f16acc(accC[mt][nt * 2 + 0], alo[mt], &bhi[0]);
                mma_f16acc(accC[mt][nt * 2 + 1], alo[mt], &bhi[2]);
            }
        }
#pragma unroll
        for (int nt = 0; nt < 4; nt++) {
            uint32_t blo[4];
            uint32_t bo = (uint32_t)((wn + nt * 16 + b_row) * SK + ks + b_kof) * 2;
            ldmatrix_x4(blo, sb + OFF_BLO + buf * B_STAGE + bo);
#pragma unroll
            for (int mt = 0; mt < 2; mt++) {
                mma_f16acc(accC[mt][nt * 2 + 0], ahi[mt], &blo[0]);
                mma_f16acc(accC[mt][nt * 2 + 1], ahi[mt], &blo[2]);
            }
        }
    };

    // prologue: chunk 0 into buf 0
    {
        issue_W(0, 0);
        float4 cz[4], bz[4];
#pragma unroll
        for (int h = 0; h < 4; h++) ldg_Z(h, 0, cz[h], bz[h]);
#pragma unroll
        for (int h = 0; h < 4; h++) sts_Z(h, 0, cz[h], bz[h]);
        cp_wait0();
        __syncthreads();
    }
    // main pipeline over 8 chunks
    for (int c = 0; c < 8; c++) {
        const int buf = c & 1;
        const int ktn = (c + 1) * TK;
        float4 cz0, bz0, cz1, bz1, cz2, bz2, cz3, bz3;
        if (c < 7) {
            issue_W(buf ^ 1, ktn);
            ldg_Z(0, ktn, cz0, bz0);
            ldg_Z(1, ktn, cz1, bz1);
        }
        mma_ks(buf, 0);
        if (c < 7) {
            sts_Z(0, buf ^ 1, cz0, bz0);
            sts_Z(1, buf ^ 1, cz1, bz1);
            ldg_Z(2, ktn, cz2, bz2);
            ldg_Z(3, ktn, cz3, bz3);
        }
        mma_ks(buf, 16);
        if (c < 7) {
            sts_Z(2, buf ^ 1, cz2, bz2);
            sts_Z(3, buf ^ 1, cz3, bz3);
            cp_wait0();
        }
        __syncthreads();
    }

    // epilogue: f32 + f16 cross + bias, clamp, int atomicMax scatter
    int* oi = (int*)out;
    const int gr = lane >> 2;
    const int gc = (lane & 3) * 2;
#pragma unroll
    for (int mt = 0; mt < 2; mt++) {
#pragma unroll
        for (int half = 0; half < 2; half++) {
            int row = wm + mt * 16 + gr + half * 8;
            int d = dstS[row];
            int base = d * HIDDEN + n0;
#pragma unroll
            for (int ns = 0; ns < 8; ns++) {
                int col = wn + ns * 8 + gc;
                __half2 ch = *(__half2*)&accC[mt][ns][half];
                float v0 = acc[mt][ns][half * 2 + 0] + __low2float(ch) + b2s[col];
                float v1 = acc[mt][ns][half * 2 + 1] + __high2float(ch) + b2s[col + 1];
                if (v0 > 0.f) atomicMax(&oi[base + col], __float_as_int(v0));
                if (v1 > 0.f) atomicMax(&oi[base + col + 1], __float_as_int(v1));
            }
        }
    }
}

// ---------------------------------------------------------------------------
extern "C" void kernel_launch(void* const* d_in, const int* in_sizes, int n_in,
                              void* d_out, int out_size) {
    const float* x = (const float*)d_in[0];
    const int* ei_raw = (const int*)d_in[1];

    static bool attr_set = false;
    if (!attr_set) {
        cudaFuncSetAttribute(edge_hmma_kernel,
                             cudaFuncAttributeMaxDynamicSharedMemorySize,
                             SM_TOTAL);
        attr_set = true;
    }

    // launch 0: index conversion
    convert_idx_auto<<<(N_EDGES + 255) / 256, 256>>>(ei_raw);
    // launch 1: all-layer W split + zero g_H0
    prep_w_all<<<5 * 256, 256>>>((const float*)d_in[4], (const float*)d_in[8],
                                 (const float*)d_in[12], (const float*)d_in[16],
                                 (const float*)d_in[20]);

    // layer l: in_sel / out_sel / zero_sel (1=H0, 2=H1, 3=d_out, 0=none)
    const int in_sel[5]   = {0, 1, 2, 1, 2};
    const int out_sel[5]  = {1, 2, 1, 2, 3};
    const int zero_sel[5] = {2, 1, 2, 3, 0};

    for (int l = 0; l < 5; l++) {
        const float* W1 = (const float*)d_in[2 + 4 * l];
        const float* b1 = (const float*)d_in[3 + 4 * l];
        const float* b2 = (const float*)d_in[5 + 4 * l];

        if (l == 0)
            node_gemm<IN_DIM><<<dim3(63, 2), 256>>>(x, W1, b1, 0);
        else
            node_gemm<HIDDEN><<<dim3(63, 2), 256>>>(x, W1, b1, in_sel[l]);

        edge_hmma_kernel<<<dim3(N_EDGES / TM, HIDDEN / TN), 256, SM_TOTAL>>>(
            b2, (float*)d_out, out_sel[l], zero_sel[l], l * HIDDEN * HIDDEN);
    }
}

// round 16
// speedup vs baseline: 2.3010x; 2.1345x over previous
#include <cuda_runtime.h>
#include <cuda_fp16.h>
#include <cstdint>

#define N_NODES 1000
#define HIDDEN  256
#define IN_DIM  128
#define N_EDGES 64000

// Scratch (device globals: no allocation allowed)
__device__ float g_C[N_NODES * HIDDEN];    // A - B + b1   (per node)
__device__ float g_B[N_NODES * HIDDEN];    // B = X @ W1b^T (per node)
__device__ float g_H0[N_NODES * HIDDEN];   // ping-pong node features
__device__ float g_H1[N_NODES * HIDDEN];
__device__ __half g_Wh[5 * HIDDEN * HIDDEN];  // W2 hi fp16, all 5 layers
__device__ __half g_Wl[5 * HIDDEN * HIDDEN];  // W2 lo fp16 residual
__device__ int   g_src[N_EDGES];
__device__ int   g_dst[N_EDGES];

// ---------------------------------------------------------------------------
__device__ __forceinline__ uint32_t smem_u32(const void* p) {
    uint32_t a;
    asm("{ .reg .u64 t; cvta.to.shared.u64 t, %1; cvt.u32.u64 %0, t; }"
        : "=r"(a) : "l"(p));
    return a;
}
__device__ __forceinline__ void ldmatrix_x4(uint32_t* r, uint32_t addr) {
    asm volatile(
        "ldmatrix.sync.aligned.m8n8.x4.shared.b16 {%0, %1, %2, %3}, [%4];"
        : "=r"(r[0]), "=r"(r[1]), "=r"(r[2]), "=r"(r[3]) : "r"(addr));
}
// fp16 inputs, fp32 accumulate
__device__ __forceinline__ void mma_f32acc(float* d, const uint32_t* a,
                                           const uint32_t* b) {
    asm volatile(
        "mma.sync.aligned.m16n8k16.row.col.f32.f16.f16.f32 "
        "{%0, %1, %2, %3}, {%4, %5, %6, %7}, {%8, %9}, {%0, %1, %2, %3};"
        : "+f"(d[0]), "+f"(d[1]), "+f"(d[2]), "+f"(d[3])
        : "r"(a[0]), "r"(a[1]), "r"(a[2]), "r"(a[3]), "r"(b[0]), "r"(b[1]));
}
__device__ __forceinline__ void cp_async16(uint32_t saddr, const void* gaddr) {
    asm volatile("cp.async.ca.shared.global [%0], [%1], 16;"
                 :: "r"(saddr), "l"(gaddr));
}
__device__ __forceinline__ void cp_commit() {
    asm volatile("cp.async.commit_group;");
}
__device__ __forceinline__ void cp_wait0() {
    asm volatile("cp.async.wait_group 0;");
}

// ---------------------------------------------------------------------------
// Self-detecting edge-index conversion (int64 vs int32), clamped.
__global__ void convert_idx_auto(const int* __restrict__ raw) {
    const unsigned int* w = (const unsigned int*)raw;
    unsigned int acc = 0;
#pragma unroll
    for (int i = 0; i < 16; i++) acc |= w[2 * i + 1];
    const bool is64 = (acc == 0u);

    int e = blockIdx.x * blockDim.x + threadIdx.x;
    if (e >= N_EDGES) return;
    int s, d;
    if (is64) { s = raw[2 * e]; d = raw[2 * (N_EDGES + e)]; }
    else      { s = raw[e];     d = raw[N_EDGES + e]; }
    g_src[e] = min(max(s, 0), N_NODES - 1);
    g_dst[e] = min(max(d, 0), N_NODES - 1);
}

// ---------------------------------------------------------------------------
// One-time: split all 5 W2 into fp16 hi/lo; also zero g_H0 (layer-0 output).
__global__ void prep_w_all(const float* __restrict__ w0, const float* __restrict__ w1,
                           const float* __restrict__ w2, const float* __restrict__ w3,
                           const float* __restrict__ w4) {
    const float* ws[5] = {w0, w1, w2, w3, w4};
    int b = blockIdx.x;           // 0..1279
    int l = b >> 8;
    int i = (b & 255) * 256 + threadIdx.x;
    float w = ws[l][i];
    __half hi = __float2half_rn(w);
    __half lo = __float2half_rn(w - __half2float(hi));
    g_Wh[l * (HIDDEN * HIDDEN) + i] = hi;
    g_Wl[l * (HIDDEN * HIDDEN) + i] = lo;
    if (b < 250) {  // 250*256 = 64000 float4 = full g_H0
        ((float4*)g_H0)[b * 256 + threadIdx.x] =
            make_float4(0.f, 0.f, 0.f, 0.f);
    }
}

// ---------------------------------------------------------------------------
// Node GEMM: C = A - B + b1, B = H @ W1b^T  (fp32, tiny: 1000x256)
// in_sel: 0 -> x, 1 -> g_H0, 2 -> g_H1
template <int DIN>
__global__ __launch_bounds__(256) void node_gemm(
    const float* __restrict__ x, const float* __restrict__ W1,
    const float* __restrict__ b1, int in_sel)
{
    const float* H = (in_sel == 0) ? x : (in_sel == 1 ? g_H0 : g_H1);
    __shared__ float Hs[16][DIN];
    const int tid = threadIdx.x;
    const int n_base = blockIdx.x * 16;

    const int nvec = 16 * DIN / 4;
    for (int i = tid; i < nvec; i += 256) {
        int row = i / (DIN / 4);
        int c4 = i % (DIN / 4);
        int n = n_base + row;
        float4 v = make_float4(0.f, 0.f, 0.f, 0.f);
        if (n < N_NODES) v = ((const float4*)(H + (size_t)n * DIN))[c4];
        ((float4*)&Hs[row][0])[c4] = v;
    }
    __syncthreads();

    const int o = blockIdx.y * 128 + (tid & 127);
    const int ng = tid >> 7;

    float accA[8], accB[8];
#pragma unroll
    for (int j = 0; j < 8; j++) { accA[j] = 0.f; accB[j] = 0.f; }

    const float4* wA4 = (const float4*)(W1 + (size_t)o * 2 * DIN);
    const float4* wB4 = (const float4*)(W1 + (size_t)o * 2 * DIN + DIN);

    for (int k4 = 0; k4 < DIN / 4; k4++) {
        float4 wa = wA4[k4];
        float4 wb = wB4[k4];
        int kk = k4 * 4;
#pragma unroll
        for (int j = 0; j < 8; j++) {
            float h0 = Hs[ng * 8 + j][kk + 0];
            float h1 = Hs[ng * 8 + j][kk + 1];
            float h2 = Hs[ng * 8 + j][kk + 2];
            float h3 = Hs[ng * 8 + j][kk + 3];
            accA[j] += h0 * wa.x + h1 * wa.y + h2 * wa.z + h3 * wa.w;
            accB[j] += h0 * wb.x + h1 * wb.y + h2 * wb.z + h3 * wb.w;
        }
    }

    float bb = b1[o];
#pragma unroll
    for (int j = 0; j < 8; j++) {
        int n = n_base + ng * 8 + j;
        if (n < N_NODES) {
            g_B[n * HIDDEN + o] = accB[j];
            g_C[n * HIDDEN + o] = accA[j] - accB[j] + bb;
        }
    }
}

// ---------------------------------------------------------------------------
// HMMA fused edge kernel (2-pass W-split fp16): 256 thr, 2 CTAs/SM,
// TM=128 x TN=128, warp tile 32x64, K=256 dbl-buffered chunks of 32.
//   z quantized to single fp16 (error ~2^-12, the only dropped term);
//   w = wh + wl exact fp16 pair; D = z*wh + z*wl, both f32 accumulate.
// 2/3 of the MMA instructions of the 3-pass kernel; half the Z convert/STS.
// Also zeros the NEXT layer's output buffer (zero_sel) — that buffer is this
// layer's node-GEMM input, already consumed (race-free, validated R15).
// out_sel/zero_sel: 0 none, 1 g_H0, 2 g_H1, 3 dout.

#define TM 128
#define TN 128
#define TK 32
#define SK 40   // padded fp16 k-stride

#define A_STAGE (TM * SK * 2)              // 10240
#define B_STAGE (TN * SK * 2)              // 10240
#define OFF_A   0                          // 2 bufs: 20480
#define OFF_BH  (2 * A_STAGE)              // 20480 (2 bufs)
#define OFF_BL  (2 * A_STAGE + 2 * B_STAGE)// 40960 (2 bufs)
#define OFF_DST (2 * A_STAGE + 4 * B_STAGE)// 61440
#define OFF_SRC (OFF_DST + 512)
#define OFF_B2  (OFF_SRC + 512)
#define SM_TOTAL (OFF_B2 + 512)            // 62976

__global__ __launch_bounds__(256, 2) void edge_hmma_kernel(
    const float* __restrict__ b2, float* __restrict__ dout,
    int out_sel, int zero_sel, int loff)
{
    extern __shared__ char smem[];
    float* out = (out_sel == 3) ? dout : (out_sel == 1 ? g_H0 : g_H1);
    const uint32_t sb = smem_u32(smem);
    const int tid = threadIdx.x;
    const int wid = tid >> 5;
    const int lane = tid & 31;
    const int e0 = blockIdx.x * TM;
    const int n0 = blockIdx.y * TN;

    // zero next layer's output buffer: 1000 CTAs x 64 float4 = 64000
    if (zero_sel != 0 && tid < 64) {
        float4* zp = (zero_sel == 3) ? (float4*)dout
                                     : (zero_sel == 1 ? (float4*)g_H0
                                                      : (float4*)g_H1);
        int cta = blockIdx.x * 2 + blockIdx.y;
        zp[cta * 64 + tid] = make_float4(0.f, 0.f, 0.f, 0.f);
    }

    int* dstS = (int*)(smem + OFF_DST);
    int* srcS = (int*)(smem + OFF_SRC);
    float* b2s = (float*)(smem + OFF_B2);

    if (tid < TM) {
        srcS[tid] = g_src[e0 + tid];
        dstS[tid] = g_dst[e0 + tid];
    }
    if (tid < TN) b2s[tid] = b2[n0 + tid];
    __syncthreads();

    const int wm = (wid >> 1) * 32;  // warp M offset (0..96)
    const int wn = (wid & 1) * 64;   // warp N offset (0 or 64)

    float acc[2][8][4];
#pragma unroll
    for (int i = 0; i < 2; i++)
#pragma unroll
        for (int j = 0; j < 8; j++)
#pragma unroll
            for (int r = 0; r < 4; r++) acc[i][j][r] = 0.f;

    const int a_row = lane & 15;
    const int a_kof = (lane >> 4) << 3;
    const int b_row = ((lane >> 4) << 3) + (lane & 7);
    const int b_kof = ((lane >> 3) & 1) << 3;

    const __half* Whp = g_Wh + loff;
    const __half* Wlp = g_Wl + loff;

    auto issue_W = [&](int buf, int kt) {
        // 2 slabs x 128 rows x 4 x 16B = 1024 tasks / 256 thr = 4 each
#pragma unroll
        for (int i = 0; i < 4; i++) {
            int id = tid + i * 256;
            int slab = id >> 9;          // 0=hi 1=lo
            int rem = id & 511;
            int row = rem >> 2;
            int q = rem & 3;
            uint32_t so = (slab ? OFF_BL : OFF_BH) + buf * B_STAGE +
                          (uint32_t)(row * SK + q * 8) * 2;
            const __half* g = slab ? Wlp : Whp;
            cp_async16(sb + so, g + (n0 + row) * HIDDEN + kt + q * 8);
        }
        cp_commit();
    };
    auto ldg_Z = [&](int h, int kt, float4& cz, float4& bz) {
        int id = tid + h * 256;
        int row = id >> 3;
        int k4 = (id & 7) * 4;
        cz = *(const float4*)&g_C[dstS[row] * HIDDEN + kt + k4];
        bz = *(const float4*)&g_B[srcS[row] * HIDDEN + kt + k4];
    };
    auto sts_Z = [&](int h, int buf, const float4& cz, const float4& bz) {
        int id = tid + h * 256;
        int row = id >> 3;
        int k4 = (id & 7) * 4;
        __half2 h01 = __floats2half2_rn(fmaxf(cz.x + bz.x, 0.f),
                                        fmaxf(cz.y + bz.y, 0.f));
        __half2 h23 = __floats2half2_rn(fmaxf(cz.z + bz.z, 0.f),
                                        fmaxf(cz.w + bz.w, 0.f));
        uint32_t eo = (uint32_t)(row * SK + k4) * 2;
        *(uint2*)(smem + OFF_A + buf * A_STAGE + eo) =
            make_uint2(*(uint32_t*)&h01, *(uint32_t*)&h23);
    };
    // 2-pass MMA: z*wh then z*wl, both into f32 acc.
    auto mma_ks = [&](int buf, int ks) {
        uint32_t a[2][4];
#pragma unroll
        for (int mt = 0; mt < 2; mt++) {
            uint32_t ao = (uint32_t)((wm + mt * 16 + a_row) * SK + ks + a_kof) * 2;
            ldmatrix_x4(a[mt], sb + OFF_A + buf * A_STAGE + ao);
        }
#pragma unroll
        for (int nt = 0; nt < 4; nt++) {
            uint32_t bh[4], bl[4];
            uint32_t bo = (uint32_t)((wn + nt * 16 + b_row) * SK + ks + b_kof) * 2;
            ldmatrix_x4(bh, sb + OFF_BH + buf * B_STAGE + bo);
            ldmatrix_x4(bl, sb + OFF_BL + buf * B_STAGE + bo);
#pragma unroll
            for (int mt = 0; mt < 2; mt++) {
                mma_f32acc(acc[mt][nt * 2 + 0], a[mt], &bh[0]);
                mma_f32acc(acc[mt][nt * 2 + 1], a[mt], &bh[2]);
                mma_f32acc(acc[mt][nt * 2 + 0], a[mt], &bl[0]);
                mma_f32acc(acc[mt][nt * 2 + 1], a[mt], &bl[2]);
            }
        }
    };

    // prologue: chunk 0 into buf 0
    {
        issue_W(0, 0);
        float4 cz[4], bz[4];
#pragma unroll
        for (int h = 0; h < 4; h++) ldg_Z(h, 0, cz[h], bz[h]);
#pragma unroll
        for (int h = 0; h < 4; h++) sts_Z(h, 0, cz[h], bz[h]);
        cp_wait0();
        __syncthreads();
    }
    // main pipeline over 8 chunks
    for (int c = 0; c < 8; c++) {
        const int buf = c & 1;
        const int ktn = (c + 1) * TK;
        float4 cz0, bz0, cz1, bz1, cz2, bz2, cz3, bz3;
        if (c < 7) {
            issue_W(buf ^ 1, ktn);
            ldg_Z(0, ktn, cz0, bz0);
            ldg_Z(1, ktn, cz1, bz1);
        }
        mma_ks(buf, 0);
        if (c < 7) {
            sts_Z(0, buf ^ 1, cz0, bz0);
            sts_Z(1, buf ^ 1, cz1, bz1);
            ldg_Z(2, ktn, cz2, bz2);
            ldg_Z(3, ktn, cz3, bz3);
        }
        mma_ks(buf, 16);
        if (c < 7) {
            sts_Z(2, buf ^ 1, cz2, bz2);
            sts_Z(3, buf ^ 1, cz3, bz3);
            cp_wait0();
        }
        __syncthreads();
    }

    // epilogue: bias, clamp, int atomicMax scatter (nonneg floats)
    int* oi = (int*)out;
    const int gr = lane >> 2;
    const int gc = (lane & 3) * 2;
#pragma unroll
    for (int mt = 0; mt < 2; mt++) {
#pragma unroll
        for (int half = 0; half < 2; half++) {
            int row = wm + mt * 16 + gr + half * 8;
            int d = dstS[row];
            int base = d * HIDDEN + n0;
#pragma unroll
            for (int ns = 0; ns < 8; ns++) {
                int col = wn + ns * 8 + gc;
                float v0 = acc[mt][ns][half * 2 + 0] + b2s[col];
                float v1 = acc[mt][ns][half * 2 + 1] + b2s[col + 1];
                if (v0 > 0.f) atomicMax(&oi[base + col], __float_as_int(v0));
                if (v1 > 0.f) atomicMax(&oi[base + col + 1], __float_as_int(v1));
            }
        }
    }
}

// ---------------------------------------------------------------------------
extern "C" void kernel_launch(void* const* d_in, const int* in_sizes, int n_in,
                              void* d_out, int out_size) {
    const float* x = (const float*)d_in[0];
    const int* ei_raw = (const int*)d_in[1];

    static bool attr_set = false;
    if (!attr_set) {
        cudaFuncSetAttribute(edge_hmma_kernel,
                             cudaFuncAttributeMaxDynamicSharedMemorySize,
                             SM_TOTAL);
        attr_set = true;
    }

    // launch 0: index conversion
    convert_idx_auto<<<(N_EDGES + 255) / 256, 256>>>(ei_raw);
    // launch 1: all-layer W split + zero g_H0
    prep_w_all<<<5 * 256, 256>>>((const float*)d_in[4], (const float*)d_in[8],
                                 (const float*)d_in[12], (const float*)d_in[16],
                                 (const float*)d_in[20]);

    // layer l: in_sel / out_sel / zero_sel (1=H0, 2=H1, 3=d_out, 0=none)
    const int in_sel[5]   = {0, 1, 2, 1, 2};
    const int out_sel[5]  = {1, 2, 1, 2, 3};
    const int zero_sel[5] = {2, 1, 2, 3, 0};

    for (int l = 0; l < 5; l++) {
        const float* W1 = (const float*)d_in[2 + 4 * l];
        const float* b1 = (const float*)d_in[3 + 4 * l];
        const float* b2 = (const float*)d_in[5 + 4 * l];

        if (l == 0)
            node_gemm<IN_DIM><<<dim3(63, 2), 256>>>(x, W1, b1, 0);
        else
            node_gemm<HIDDEN><<<dim3(63, 2), 256>>>(x, W1, b1, in_sel[l]);

        edge_hmma_kernel<<<dim3(N_EDGES / TM, HIDDEN / TN), 256, SM_TOTAL>>>(
            b2, (float*)d_out, out_sel[l], zero_sel[l], l * HIDDEN * HIDDEN);
    }
}